// round 13
// baseline (speedup 1.0000x reference)
#include <cuda_runtime.h>
#include <cuda_fp16.h>
#include <cstdint>
#include <cstddef>

#define BATCH   65536
#define EMBED   128
#define NSP     26
#define VOCABM  0xFFFFF  // VOCAB-1, VOCAB = 2^20

// ---------------- scratch (device globals: allocation-free rule) ----------------
__device__ __half g_bufA[(size_t)BATCH * 1024];  // 128 MB (half activations)
__device__ __half g_bufB[(size_t)BATCH * 1024];  // 128 MB
__device__ __half g_h  [(size_t)BATCH * 128];    // 16 MB
__device__ __half g_wt [2392064];                // transposed fp16 weights, ~4.8 MB

// transposed-weight offsets (half elements)
#define WT_BW1 0
#define WT_BW2 131072
#define WT_TW0 163840
#define WT_TW1 688128
#define WT_TW2 1736704
#define WT_TW3 2260992

// ---------------- helpers ----------------
__device__ __forceinline__ uint32_t smem_u32(const void* p) {
    uint32_t a;
    asm("{ .reg .u64 t; cvta.to.shared.u64 t, %1; cvt.u32.u64 %0, t; }" : "=r"(a) : "l"(p));
    return a;
}

__device__ __forceinline__ void mma16(float d[4], const unsigned a[4], const unsigned b[2]) {
    asm volatile(
        "mma.sync.aligned.m16n8k16.row.col.f32.f16.f16.f32 "
        "{%0,%1,%2,%3}, {%4,%5,%6,%7}, {%8,%9}, {%0,%1,%2,%3};\n"
        : "+f"(d[0]), "+f"(d[1]), "+f"(d[2]), "+f"(d[3])
        : "r"(a[0]), "r"(a[1]), "r"(a[2]), "r"(a[3]), "r"(b[0]), "r"(b[1]));
}

__device__ __forceinline__ void ldsm4(unsigned r[4], uint32_t addr) {
    asm volatile("ldmatrix.sync.aligned.m8n8.x4.shared.b16 {%0,%1,%2,%3}, [%4];"
                 : "=r"(r[0]), "=r"(r[1]), "=r"(r[2]), "=r"(r[3]) : "r"(addr));
}

#define CPA16(dst, src) \
    asm volatile("cp.async.cg.shared.global [%0], [%1], 16;" :: "r"(dst), "l"(src))
#define CPA_COMMIT() asm volatile("cp.async.commit_group;" ::: "memory")
#define CPA_WAIT1()  asm volatile("cp.async.wait_group 1;" ::: "memory")

// =====================================================================
// Weight transpose + fp16 convert: wt[n*Kpad + k] = h(w[k*N + n]), 0 pad.
// =====================================================================
__global__ void transpose_w(const float* __restrict__ w, __half* __restrict__ wt,
                            int K, int N, int Kpad)
{
    __shared__ float ts[32][33];
    const int k0 = blockIdx.x * 32;
    const int n0 = blockIdx.y * 32;
    const int tx = threadIdx.x, ty = threadIdx.y;
    #pragma unroll
    for (int i = 0; i < 32; i += 8) {
        const int k = k0 + ty + i;
        ts[ty + i][tx] = (k < K) ? w[(size_t)k * N + n0 + tx] : 0.f;
    }
    __syncthreads();
    #pragma unroll
    for (int i = 0; i < 32; i += 8) {
        const int n = n0 + ty + i;
        wt[(size_t)n * Kpad + k0 + tx] = __float2half_rn(ts[tx][ty + i]);
    }
}

// =====================================================================
// Bottom layer 0: [65536 x 13] @ [13 x 512] + b, relu. K tiny -> SIMT.
// =====================================================================
__global__ __launch_bounds__(256) void bottom0_kernel(
    const float* __restrict__ dense, const float* __restrict__ w,
    const float* __restrict__ bias, __half* __restrict__ out)
{
    __shared__ float ws[13 * 512];
    __shared__ float bs[512];
    __shared__ float as[32][14];

    const int tid = threadIdx.x;
    const int m0  = blockIdx.x * 32;

    for (int i = tid; i < (13 * 512) / 4; i += 256)
        ((float4*)ws)[i] = ((const float4*)w)[i];
    if (tid < 128) ((float4*)bs)[tid] = ((const float4*)bias)[tid];
    for (int i = tid; i < 32 * 13; i += 256)
        as[i / 13][i % 13] = dense[(size_t)(m0 + i / 13) * 13 + (i % 13)];
    __syncthreads();

    const int n     = (tid & 127) * 4;
    const int rbase = (tid >> 7) * 16;
    const float4 bv = *(const float4*)(bs + n);

    for (int rr = 0; rr < 16; ++rr) {
        const int r = rbase + rr;
        float4 acc = bv;
        #pragma unroll
        for (int k = 0; k < 13; ++k) {
            const float av = as[r][k];
            const float4 wv = *(const float4*)(ws + k * 512 + n);
            acc.x += av * wv.x; acc.y += av * wv.y;
            acc.z += av * wv.z; acc.w += av * wv.w;
        }
        __half2 h01 = __floats2half2_rn(fmaxf(acc.x, 0.f), fmaxf(acc.y, 0.f));
        __half2 h23 = __floats2half2_rn(fmaxf(acc.z, 0.f), fmaxf(acc.w, 0.f));
        __half2* op = (__half2*)(out + (size_t)(m0 + r) * 512 + n);
        op[0] = h01;
        op[1] = h23;
    }
}

// =====================================================================
// FP16 GEMM v2: cp.async 3-stage pipeline + ldmatrix + wide N tiles.
// Block tile 128 x (WN*32) x 32; warps 2 x WN; warp tile 64x32.
// WN=8 -> 512 threads, 90KB smem.  WN=4 -> 256 threads, 60KB smem.
// K must be a multiple of 32 (zero-padded). All half I/O.
// =====================================================================
#define APAD   40
#define STAGES 3

template<int WN>
__global__ __launch_bounds__(64 * WN, 1) void gemm_fp16(
    const __half* __restrict__ A, int lda,
    const __half* __restrict__ Wt,
    const float* __restrict__ bias,
    __half* __restrict__ C, int ldc,
    int K, int doRelu)
{
    constexpr int NT = WN * 32;        // N tile
    constexpr int T  = 64 * WN;        // threads
    constexpr int AC = 512;            // A 16B-chunks per stage (128*32/8)
    constexpr int BC = NT * 4;         // B 16B-chunks per stage

    extern __shared__ __align__(16) __half dsm[];
    __half* Asm = dsm;                           // [STAGES][128][APAD]
    __half* Bsm = dsm + STAGES * 128 * APAD;     // [STAGES][NT][APAD]

    const int tid  = threadIdx.x;
    const int m0   = blockIdx.y * 128;
    const int n0   = blockIdx.x * NT;
    const int warp = tid >> 5;
    const int lane = tid & 31;
    const int wm   = warp / WN;        // 0..1
    const int wn   = warp % WN;        // 0..WN-1
    const int grp  = lane >> 2;
    const int qid  = lane & 3;

    const uint32_t sA = smem_u32(Asm);
    const uint32_t sB = smem_u32(Bsm);

    // ldmatrix per-lane offsets
    const int arow = (lane & 7) + ((lane >> 3) & 1) * 8;
    const int acol = (lane >> 4) * 8;
    const int brow = (lane & 7) + (lane >> 4) * 8;
    const int bcol = ((lane >> 3) & 1) * 8;

    const int nkt = K >> 5;

    float acc[4][4][4];
    #pragma unroll
    for (int i = 0; i < 4; ++i)
        #pragma unroll
        for (int j = 0; j < 4; ++j)
            #pragma unroll
            for (int r = 0; r < 4; ++r) acc[i][j][r] = 0.f;

    // stage issue: cp.async the (kt)-th k-tile into buffer s
    auto issue = [&](int kt, int s) {
        const int k0 = kt * 32;
        #pragma unroll
        for (int c = tid; c < AC; c += T) {
            const int r = c >> 2, j = (c & 3) * 8;
            CPA16(sA + (uint32_t)(((s * 128 + r) * APAD) + j) * 2,
                  A + (size_t)(m0 + r) * lda + k0 + j);
        }
        #pragma unroll
        for (int c = tid; c < BC; c += T) {
            const int r = c >> 2, j = (c & 3) * 8;
            CPA16(sB + (uint32_t)(((s * NT + r) * APAD) + j) * 2,
                  Wt + (size_t)(n0 + r) * K + k0 + j);
        }
        CPA_COMMIT();
    };

    issue(0, 0);
    if (nkt > 1) issue(1, 1); else CPA_COMMIT();

    for (int kt = 0; kt < nkt; ++kt) {
        const int buf = kt % STAGES;
        CPA_WAIT1();
        __syncthreads();

        // prefetch next+1 stage (its buffer was consumed 1 iteration ago;
        // the syncthreads above guarantees all warps are past it)
        if (kt + 2 < nkt) issue(kt + 2, (kt + 2) % STAGES);
        else CPA_COMMIT();

        #pragma unroll
        for (int ks = 0; ks < 2; ++ks) {
            const int kb = ks * 16;
            unsigned af[4][4], bq0[4], bq1[4];
            const uint32_t aa = sA + (uint32_t)(((buf * 128 + wm * 64 + arow) * APAD) + kb + acol) * 2;
            #pragma unroll
            for (int mt = 0; mt < 4; ++mt)
                ldsm4(af[mt], aa + (uint32_t)(mt * 16 * APAD) * 2);
            const uint32_t ba = sB + (uint32_t)(((buf * NT + wn * 32 + brow) * APAD) + kb + bcol) * 2;
            ldsm4(bq0, ba);
            ldsm4(bq1, ba + (uint32_t)(16 * APAD) * 2);

            #pragma unroll
            for (int mt = 0; mt < 4; ++mt) {
                mma16(acc[mt][0], af[mt], &bq0[0]);
                mma16(acc[mt][1], af[mt], &bq0[2]);
                mma16(acc[mt][2], af[mt], &bq1[0]);
                mma16(acc[mt][3], af[mt], &bq1[2]);
            }
        }
    }

    // epilogue: bias + relu + half2 store
    #pragma unroll
    for (int nt = 0; nt < 4; ++nt) {
        const int cc = n0 + wn * 32 + nt * 8 + qid * 2;
        const float b0 = bias[cc];
        const float b1 = bias[cc + 1];
        #pragma unroll
        for (int mt = 0; mt < 4; ++mt) {
            const int rr = m0 + wm * 64 + mt * 16 + grp;
            float v0 = acc[mt][nt][0] + b0;
            float v1 = acc[mt][nt][1] + b1;
            float v2 = acc[mt][nt][2] + b0;
            float v3 = acc[mt][nt][3] + b1;
            if (doRelu) {
                v0 = fmaxf(v0, 0.f); v1 = fmaxf(v1, 0.f);
                v2 = fmaxf(v2, 0.f); v3 = fmaxf(v3, 0.f);
            }
            *(__half2*)(C + (size_t)rr * ldc + cc)       = __floats2half2_rn(v0, v1);
            *(__half2*)(C + (size_t)(rr + 8) * ldc + cc) = __floats2half2_rn(v2, v3);
        }
    }
}

#define SMEM8 (STAGES * (128 + 256) * APAD * 2)  // 92160
#define SMEM4 (STAGES * (128 + 128) * APAD * 2)  // 61440

// =====================================================================
// Fused: embedding gather + self-interaction + top_in assembly.
// fp16 combined tile in smem, Gram via fp16 mma + ldmatrix.
// =====================================================================
#define IPAD 136

__device__ __forceinline__ void triu_store(__half* orow, int i, int j, float v) {
    if (i < 27 && j < 27 && i <= j) {
        const int pos = i * 27 - (i * (i - 1)) / 2 + (j - i);
        orow[pos] = __float2half_rn(v);
    }
}

__global__ __launch_bounds__(128) void interact_kernel(
    const float*  __restrict__ emb,
    const int*    __restrict__ sidx,
    const __half* __restrict__ h,
    __half* __restrict__ topin)
{
    __shared__ __half cs[4][32 * IPAD];
    const int warp = threadIdx.x >> 5;
    const int lane = threadIdx.x & 31;
    const size_t s = (size_t)blockIdx.x * 4 + warp;
    __half* c = cs[warp];
    const int grp = lane >> 2;
    const int qid = lane & 3;

    int myidx = 0;
    if (lane < NSP) myidx = sidx[s * NSP + lane] & VOCABM;

    {
        const uint2 hraw = *(const uint2*)(h + s * 128 + lane * 4);
        *(uint2*)(topin + s * 512 + lane * 4) = hraw;
        *(uint2*)(c + lane * 4) = hraw;
    }

    for (int r = 1; r <= NSP; ++r) {
        const int idx = __shfl_sync(0xffffffffu, myidx, r - 1);
        const float4 v = *(const float4*)(emb + (size_t)idx * 128 + lane * 4);
        __half2 p0 = __floats2half2_rn(v.x, v.y);
        __half2 p1 = __floats2half2_rn(v.z, v.w);
        *(uint2*)(c + r * IPAD + lane * 4) =
            make_uint2(*(unsigned*)&p0, *(unsigned*)&p1);
    }
    const uint2 z2 = make_uint2(0u, 0u);
    #pragma unroll
    for (int r = 27; r < 32; ++r) *(uint2*)(c + r * IPAD + lane * 4) = z2;
    if (lane < 6) topin[s * 512 + 506 + lane] = __float2half_rn(0.f);
    __syncwarp();

    const int arow = (lane & 7) + ((lane >> 3) & 1) * 8;
    const int acol = (lane >> 4) * 8;
    const int brow = (lane & 7) + (lane >> 4) * 8;
    const int bcol = ((lane >> 3) & 1) * 8;
    const uint32_t cb = smem_u32(c);

    float acc[6][4];
    #pragma unroll
    for (int t = 0; t < 6; ++t)
        #pragma unroll
        for (int r = 0; r < 4; ++r) acc[t][r] = 0.f;

    #pragma unroll
    for (int kk = 0; kk < 8; ++kk) {
        const int kb = kk * 16;
        unsigned a0[4], a1[4], bq0[4], bq1[4];
        const uint32_t aa = cb + (uint32_t)(arow * IPAD + kb + acol) * 2;
        ldsm4(a0, aa);
        ldsm4(a1, aa + (uint32_t)(16 * IPAD) * 2);
        const uint32_t ba = cb + (uint32_t)(brow * IPAD + kb + bcol) * 2;
        ldsm4(bq0, ba);
        ldsm4(bq1, ba + (uint32_t)(16 * IPAD) * 2);

        mma16(acc[0], a0, &bq0[0]);
        mma16(acc[1], a0, &bq0[2]);
        mma16(acc[2], a0, &bq1[0]);
        mma16(acc[3], a0, &bq1[2]);
        mma16(acc[4], a1, &bq1[0]);
        mma16(acc[5], a1, &bq1[2]);
    }

    __half* orow = topin + s * 512 + 128;
    const int tmi[6] = {0, 0, 0, 0, 1, 1};
    const int tni[6] = {0, 1, 2, 3, 2, 3};
    #pragma unroll
    for (int t = 0; t < 6; ++t) {
        const int i0 = tmi[t] * 16 + grp;
        const int j0 = tni[t] * 8 + qid * 2;
        triu_store(orow, i0,     j0,     acc[t][0]);
        triu_store(orow, i0,     j0 + 1, acc[t][1]);
        triu_store(orow, i0 + 8, j0,     acc[t][2]);
        triu_store(orow, i0 + 8, j0 + 1, acc[t][3]);
    }
}

// =====================================================================
// Final layer: [65536 x 256] half @ [256 x 1] f32 + b. Warp per row.
// =====================================================================
__global__ __launch_bounds__(256) void gemv_final_kernel(
    const __half* __restrict__ X, const float* __restrict__ w,
    const float* __restrict__ b, float* __restrict__ out)
{
    __shared__ float ws[256];
    const int tid = threadIdx.x;
    if (tid < 64) ((float4*)ws)[tid] = ((const float4*)w)[tid];
    __syncthreads();

    const int warp = tid >> 5;
    const int lane = tid & 31;
    const size_t row = (size_t)blockIdx.x * 8 + warp;
    const __half* x = X + row * 256;

    float sum = 0.f;
    #pragma unroll
    for (int i = 0; i < 8; ++i)
        sum += __half2float(x[lane + i * 32]) * ws[lane + i * 32];
    #pragma unroll
    for (int off = 16; off; off >>= 1) sum += __shfl_xor_sync(0xffffffffu, sum, off);
    if (lane == 0) out[row] = sum + b[0];
}

// =====================================================================
// Launch
// =====================================================================
extern "C" void kernel_launch(void* const* d_in, const int* in_sizes, int n_in,
                              void* d_out, int out_size)
{
    (void)in_sizes; (void)n_in; (void)out_size;
    const float* dense = (const float*)d_in[0];
    const int*   sidx  = (const int*)d_in[1];
    const float* emb   = (const float*)d_in[2];
    const float* bw0 = (const float*)d_in[3];
    const float* bb0 = (const float*)d_in[4];
    const float* bw1 = (const float*)d_in[5];
    const float* bb1 = (const float*)d_in[6];
    const float* bw2 = (const float*)d_in[7];
    const float* bb2 = (const float*)d_in[8];
    const float* tw0 = (const float*)d_in[9];
    const float* tb0 = (const float*)d_in[10];
    const float* tw1 = (const float*)d_in[11];
    const float* tb1 = (const float*)d_in[12];
    const float* tw2 = (const float*)d_in[13];
    const float* tb2 = (const float*)d_in[14];
    const float* tw3 = (const float*)d_in[15];
    const float* tb3 = (const float*)d_in[16];
    const float* tw4 = (const float*)d_in[17];
    const float* tb4 = (const float*)d_in[18];
    float* out = (float*)d_out;

    __half *A = nullptr, *B = nullptr, *H = nullptr, *WT = nullptr;
    cudaGetSymbolAddress((void**)&A, g_bufA);
    cudaGetSymbolAddress((void**)&B, g_bufB);
    cudaGetSymbolAddress((void**)&H, g_h);
    cudaGetSymbolAddress((void**)&WT, g_wt);

    static int attr_done = 0;
    if (!attr_done) {
        cudaFuncSetAttribute(gemm_fp16<8>, cudaFuncAttributeMaxDynamicSharedMemorySize, SMEM8);
        cudaFuncSetAttribute(gemm_fp16<4>, cudaFuncAttributeMaxDynamicSharedMemorySize, SMEM4);
        attr_done = 1;
    }

    const dim3 tb(32, 8);
    transpose_w<<<dim3(16, 8),  tb>>>(bw1, WT + WT_BW1, 512,  256,  512);
    transpose_w<<<dim3(8, 4),   tb>>>(bw2, WT + WT_BW2, 256,  128,  256);
    transpose_w<<<dim3(16, 32), tb>>>(tw0, WT + WT_TW0, 506,  1024, 512);
    transpose_w<<<dim3(32, 32), tb>>>(tw1, WT + WT_TW1, 1024, 1024, 1024);
    transpose_w<<<dim3(32, 16), tb>>>(tw2, WT + WT_TW2, 1024, 512,  1024);
    transpose_w<<<dim3(16, 8),  tb>>>(tw3, WT + WT_TW3, 512,  256,  512);

    const int MB = BATCH / 128;  // 512

    // bottom MLP: 13 -> 512 -> 256 -> 128 (relu)
    bottom0_kernel<<<BATCH / 32, 256>>>(dense, bw0, bb0, A);
    gemm_fp16<8><<<dim3(1, MB), 512, SMEM8>>>(A, 512, WT + WT_BW1, bb1, B, 256, 512, 1);
    gemm_fp16<4><<<dim3(1, MB), 256, SMEM4>>>(B, 256, WT + WT_BW2, bb2, H, 128, 256, 1);

    // gather + interaction + top_in assembly
    interact_kernel<<<BATCH / 4, 128>>>(emb, sidx, H, A);

    // top MLP: 506(pad 512) -> 1024 -> 1024 -> 512 -> 256 (relu) -> 1
    gemm_fp16<8><<<dim3(4, MB), 512, SMEM8>>>(A, 512,  WT + WT_TW0, tb0, B, 1024, 512,  1);
    gemm_fp16<8><<<dim3(4, MB), 512, SMEM8>>>(B, 1024, WT + WT_TW1, tb1, A, 1024, 1024, 1);
    gemm_fp16<8><<<dim3(2, MB), 512, SMEM8>>>(A, 1024, WT + WT_TW2, tb2, B, 512,  1024, 1);
    gemm_fp16<8><<<dim3(1, MB), 512, SMEM8>>>(B, 512,  WT + WT_TW3, tb3, A, 256,  512,  1);
    gemv_final_kernel<<<BATCH / 8, 256>>>(A, tw4, tb4, out);
}

// round 14
// speedup vs baseline: 1.1764x; 1.1764x over previous
#include <cuda_runtime.h>
#include <cuda_fp16.h>
#include <cstdint>
#include <cstddef>

#define BATCH   65536
#define EMBED   128
#define NSP     26
#define VOCABM  0xFFFFF  // VOCAB-1, VOCAB = 2^20

// ---------------- scratch (device globals: allocation-free rule) ----------------
__device__ __half g_bufA[(size_t)BATCH * 1024];  // 128 MB (half activations)
__device__ __half g_bufB[(size_t)BATCH * 1024];  // 128 MB
__device__ __half g_h  [(size_t)BATCH * 128];    // 16 MB
__device__ __half g_wt [2392064];                // transposed fp16 weights, ~4.8 MB

// transposed-weight offsets (half elements)
#define WT_BW1 0
#define WT_BW2 131072
#define WT_TW0 163840
#define WT_TW1 688128
#define WT_TW2 1736704
#define WT_TW3 2260992

// ---------------- helpers ----------------
__device__ __forceinline__ uint32_t smem_u32(const void* p) {
    uint32_t a;
    asm("{ .reg .u64 t; cvta.to.shared.u64 t, %1; cvt.u32.u64 %0, t; }" : "=r"(a) : "l"(p));
    return a;
}

__device__ __forceinline__ void mma16(float d[4], const unsigned a[4], const unsigned b[2]) {
    asm volatile(
        "mma.sync.aligned.m16n8k16.row.col.f32.f16.f16.f32 "
        "{%0,%1,%2,%3}, {%4,%5,%6,%7}, {%8,%9}, {%0,%1,%2,%3};\n"
        : "+f"(d[0]), "+f"(d[1]), "+f"(d[2]), "+f"(d[3])
        : "r"(a[0]), "r"(a[1]), "r"(a[2]), "r"(a[3]), "r"(b[0]), "r"(b[1]));
}

__device__ __forceinline__ void ldsm4(unsigned r[4], uint32_t addr) {
    asm volatile("ldmatrix.sync.aligned.m8n8.x4.shared.b16 {%0,%1,%2,%3}, [%4];"
                 : "=r"(r[0]), "=r"(r[1]), "=r"(r[2]), "=r"(r[3]) : "r"(addr));
}

#define CPA16(dst, src) \
    asm volatile("cp.async.cg.shared.global [%0], [%1], 16;" :: "r"(dst), "l"(src))
#define CPA_COMMIT() asm volatile("cp.async.commit_group;" ::: "memory")
#define CPA_WAIT1()  asm volatile("cp.async.wait_group 1;" ::: "memory")

// =====================================================================
// Weight transpose + fp16 convert: wt[n*Kpad + k] = h(w[k*N + n]), 0 pad.
// =====================================================================
__global__ void transpose_w(const float* __restrict__ w, __half* __restrict__ wt,
                            int K, int N, int Kpad)
{
    __shared__ float ts[32][33];
    const int k0 = blockIdx.x * 32;
    const int n0 = blockIdx.y * 32;
    const int tx = threadIdx.x, ty = threadIdx.y;
    #pragma unroll
    for (int i = 0; i < 32; i += 8) {
        const int k = k0 + ty + i;
        ts[ty + i][tx] = (k < K) ? w[(size_t)k * N + n0 + tx] : 0.f;
    }
    __syncthreads();
    #pragma unroll
    for (int i = 0; i < 32; i += 8) {
        const int n = n0 + ty + i;
        wt[(size_t)n * Kpad + k0 + tx] = __float2half_rn(ts[tx][ty + i]);
    }
}

// =====================================================================
// Bottom layer 0: [65536 x 13] @ [13 x 512] + b, relu. K tiny -> SIMT.
// =====================================================================
__global__ __launch_bounds__(256) void bottom0_kernel(
    const float* __restrict__ dense, const float* __restrict__ w,
    const float* __restrict__ bias, __half* __restrict__ out)
{
    __shared__ float ws[13 * 512];
    __shared__ float bs[512];
    __shared__ float as[32][14];

    const int tid = threadIdx.x;
    const int m0  = blockIdx.x * 32;

    for (int i = tid; i < (13 * 512) / 4; i += 256)
        ((float4*)ws)[i] = ((const float4*)w)[i];
    if (tid < 128) ((float4*)bs)[tid] = ((const float4*)bias)[tid];
    for (int i = tid; i < 32 * 13; i += 256)
        as[i / 13][i % 13] = dense[(size_t)(m0 + i / 13) * 13 + (i % 13)];
    __syncthreads();

    const int n     = (tid & 127) * 4;
    const int rbase = (tid >> 7) * 16;
    const float4 bv = *(const float4*)(bs + n);

    for (int rr = 0; rr < 16; ++rr) {
        const int r = rbase + rr;
        float4 acc = bv;
        #pragma unroll
        for (int k = 0; k < 13; ++k) {
            const float av = as[r][k];
            const float4 wv = *(const float4*)(ws + k * 512 + n);
            acc.x += av * wv.x; acc.y += av * wv.y;
            acc.z += av * wv.z; acc.w += av * wv.w;
        }
        __half2 h01 = __floats2half2_rn(fmaxf(acc.x, 0.f), fmaxf(acc.y, 0.f));
        __half2 h23 = __floats2half2_rn(fmaxf(acc.z, 0.f), fmaxf(acc.w, 0.f));
        __half2* op = (__half2*)(out + (size_t)(m0 + r) * 512 + n);
        op[0] = h01;
        op[1] = h23;
    }
}

// =====================================================================
// FP16 GEMM v3: round-12 shape (128x128x32 tile, 256 thr, 8 warps,
// warp tile 64x32, 2 CTAs/SM) + cp.async 3-stage pipeline.
// K multiple of 32 (zero-padded). All half I/O.
// =====================================================================
#define APAD   40
#define STAGES 3
#define GSMEM  (STAGES * (128 + 128) * APAD * 2)  // 61440 bytes

__global__ __launch_bounds__(256, 2) void gemm_fp16(
    const __half* __restrict__ A, int lda,
    const __half* __restrict__ Wt,
    const float* __restrict__ bias,
    __half* __restrict__ C, int ldc,
    int K, int doRelu)
{
    extern __shared__ __align__(16) __half dsm[];
    __half* Asm = dsm;                           // [STAGES][128][APAD]
    __half* Bsm = dsm + STAGES * 128 * APAD;     // [STAGES][128][APAD]

    const int tid  = threadIdx.x;
    const int m0   = blockIdx.y * 128;
    const int n0   = blockIdx.x * 128;
    const int warp = tid >> 5;
    const int lane = tid & 31;
    const int wm   = warp >> 2;   // 0..1
    const int wn   = warp & 3;    // 0..3
    const int grp  = lane >> 2;
    const int qid  = lane & 3;

    const uint32_t sA = smem_u32(Asm);
    const uint32_t sB = smem_u32(Bsm);

    // per-thread staging coords: 2 chunks per side per stage
    const int sr = tid >> 2;       // 0..63 (+64 second chunk)
    const int sj = (tid & 3) * 8;  // 0,8,16,24

    // ldmatrix per-lane offsets
    const int arow = (lane & 7) + ((lane >> 3) & 1) * 8;
    const int acol = (lane >> 4) * 8;
    const int brow = (lane & 7) + (lane >> 4) * 8;
    const int bcol = ((lane >> 3) & 1) * 8;

    const int nkt = K >> 5;

    float acc[4][4][4];
    #pragma unroll
    for (int i = 0; i < 4; ++i)
        #pragma unroll
        for (int j = 0; j < 4; ++j)
            #pragma unroll
            for (int r = 0; r < 4; ++r) acc[i][j][r] = 0.f;

    // issue the kt-th k-tile into stage buffer s
    auto issue = [&](int kt, int s) {
        const int k0 = kt * 32;
        const __half* ap = A + (size_t)(m0 + sr) * lda + k0 + sj;
        CPA16(sA + (uint32_t)(((s * 128 + sr) * APAD) + sj) * 2, ap);
        CPA16(sA + (uint32_t)(((s * 128 + sr + 64) * APAD) + sj) * 2,
              ap + (size_t)64 * lda);
        const __half* bp = Wt + (size_t)(n0 + sr) * K + k0 + sj;
        CPA16(sB + (uint32_t)(((s * 128 + sr) * APAD) + sj) * 2, bp);
        CPA16(sB + (uint32_t)(((s * 128 + sr + 64) * APAD) + sj) * 2,
              bp + (size_t)64 * K);
        CPA_COMMIT();
    };

    issue(0, 0);
    if (nkt > 1) issue(1, 1); else CPA_COMMIT();

    for (int kt = 0; kt < nkt; ++kt) {
        const int buf = kt % STAGES;
        CPA_WAIT1();
        __syncthreads();

        // prefetch kt+2 into its buffer (consumed at kt-1; sync above makes it free)
        if (kt + 2 < nkt) issue(kt + 2, (kt + 2) % STAGES);
        else CPA_COMMIT();

        #pragma unroll
        for (int ks = 0; ks < 2; ++ks) {
            const int kb = ks * 16;
            unsigned af[4][4], bq0[4], bq1[4];
            const uint32_t aa = sA + (uint32_t)(((buf * 128 + wm * 64 + arow) * APAD) + kb + acol) * 2;
            #pragma unroll
            for (int mt = 0; mt < 4; ++mt)
                ldsm4(af[mt], aa + (uint32_t)(mt * 16 * APAD) * 2);
            const uint32_t ba = sB + (uint32_t)(((buf * 128 + wn * 32 + brow) * APAD) + kb + bcol) * 2;
            ldsm4(bq0, ba);
            ldsm4(bq1, ba + (uint32_t)(16 * APAD) * 2);

            #pragma unroll
            for (int mt = 0; mt < 4; ++mt) {
                mma16(acc[mt][0], af[mt], &bq0[0]);
                mma16(acc[mt][1], af[mt], &bq0[2]);
                mma16(acc[mt][2], af[mt], &bq1[0]);
                mma16(acc[mt][3], af[mt], &bq1[2]);
            }
        }
    }

    // epilogue: bias + relu + half2 store
    #pragma unroll
    for (int nt = 0; nt < 4; ++nt) {
        const int cc = n0 + wn * 32 + nt * 8 + qid * 2;
        const float b0 = bias[cc];
        const float b1 = bias[cc + 1];
        #pragma unroll
        for (int mt = 0; mt < 4; ++mt) {
            const int rr = m0 + wm * 64 + mt * 16 + grp;
            float v0 = acc[mt][nt][0] + b0;
            float v1 = acc[mt][nt][1] + b1;
            float v2 = acc[mt][nt][2] + b0;
            float v3 = acc[mt][nt][3] + b1;
            if (doRelu) {
                v0 = fmaxf(v0, 0.f); v1 = fmaxf(v1, 0.f);
                v2 = fmaxf(v2, 0.f); v3 = fmaxf(v3, 0.f);
            }
            *(__half2*)(C + (size_t)rr * ldc + cc)       = __floats2half2_rn(v0, v1);
            *(__half2*)(C + (size_t)(rr + 8) * ldc + cc) = __floats2half2_rn(v2, v3);
        }
    }
}

// =====================================================================
// Fused: embedding gather + self-interaction + top_in assembly.
// =====================================================================
#define IPAD 136

__device__ __forceinline__ void triu_store(__half* orow, int i, int j, float v) {
    if (i < 27 && j < 27 && i <= j) {
        const int pos = i * 27 - (i * (i - 1)) / 2 + (j - i);
        orow[pos] = __float2half_rn(v);
    }
}

__global__ __launch_bounds__(128) void interact_kernel(
    const float*  __restrict__ emb,
    const int*    __restrict__ sidx,
    const __half* __restrict__ h,
    __half* __restrict__ topin)
{
    __shared__ __half cs[4][32 * IPAD];
    const int warp = threadIdx.x >> 5;
    const int lane = threadIdx.x & 31;
    const size_t s = (size_t)blockIdx.x * 4 + warp;
    __half* c = cs[warp];
    const int grp = lane >> 2;
    const int qid = lane & 3;

    int myidx = 0;
    if (lane < NSP) myidx = sidx[s * NSP + lane] & VOCABM;

    {
        const uint2 hraw = *(const uint2*)(h + s * 128 + lane * 4);
        *(uint2*)(topin + s * 512 + lane * 4) = hraw;
        *(uint2*)(c + lane * 4) = hraw;
    }

    for (int r = 1; r <= NSP; ++r) {
        const int idx = __shfl_sync(0xffffffffu, myidx, r - 1);
        const float4 v = *(const float4*)(emb + (size_t)idx * 128 + lane * 4);
        __half2 p0 = __floats2half2_rn(v.x, v.y);
        __half2 p1 = __floats2half2_rn(v.z, v.w);
        *(uint2*)(c + r * IPAD + lane * 4) =
            make_uint2(*(unsigned*)&p0, *(unsigned*)&p1);
    }
    const uint2 z2 = make_uint2(0u, 0u);
    #pragma unroll
    for (int r = 27; r < 32; ++r) *(uint2*)(c + r * IPAD + lane * 4) = z2;
    if (lane < 6) topin[s * 512 + 506 + lane] = __float2half_rn(0.f);
    __syncwarp();

    const int arow = (lane & 7) + ((lane >> 3) & 1) * 8;
    const int acol = (lane >> 4) * 8;
    const int brow = (lane & 7) + (lane >> 4) * 8;
    const int bcol = ((lane >> 3) & 1) * 8;
    const uint32_t cb = smem_u32(c);

    float acc[6][4];
    #pragma unroll
    for (int t = 0; t < 6; ++t)
        #pragma unroll
        for (int r = 0; r < 4; ++r) acc[t][r] = 0.f;

    #pragma unroll
    for (int kk = 0; kk < 8; ++kk) {
        const int kb = kk * 16;
        unsigned a0[4], a1[4], bq0[4], bq1[4];
        const uint32_t aa = cb + (uint32_t)(arow * IPAD + kb + acol) * 2;
        ldsm4(a0, aa);
        ldsm4(a1, aa + (uint32_t)(16 * IPAD) * 2);
        const uint32_t ba = cb + (uint32_t)(brow * IPAD + kb + bcol) * 2;
        ldsm4(bq0, ba);
        ldsm4(bq1, ba + (uint32_t)(16 * IPAD) * 2);

        mma16(acc[0], a0, &bq0[0]);
        mma16(acc[1], a0, &bq0[2]);
        mma16(acc[2], a0, &bq1[0]);
        mma16(acc[3], a0, &bq1[2]);
        mma16(acc[4], a1, &bq1[0]);
        mma16(acc[5], a1, &bq1[2]);
    }

    __half* orow = topin + s * 512 + 128;
    const int tmi[6] = {0, 0, 0, 0, 1, 1};
    const int tni[6] = {0, 1, 2, 3, 2, 3};
    #pragma unroll
    for (int t = 0; t < 6; ++t) {
        const int i0 = tmi[t] * 16 + grp;
        const int j0 = tni[t] * 8 + qid * 2;
        triu_store(orow, i0,     j0,     acc[t][0]);
        triu_store(orow, i0,     j0 + 1, acc[t][1]);
        triu_store(orow, i0 + 8, j0,     acc[t][2]);
        triu_store(orow, i0 + 8, j0 + 1, acc[t][3]);
    }
}

// =====================================================================
// Final layer: [65536 x 256] half @ [256 x 1] f32 + b. Warp per row.
// =====================================================================
__global__ __launch_bounds__(256) void gemv_final_kernel(
    const __half* __restrict__ X, const float* __restrict__ w,
    const float* __restrict__ b, float* __restrict__ out)
{
    __shared__ float ws[256];
    const int tid = threadIdx.x;
    if (tid < 64) ((float4*)ws)[tid] = ((const float4*)w)[tid];
    __syncthreads();

    const int warp = tid >> 5;
    const int lane = tid & 31;
    const size_t row = (size_t)blockIdx.x * 8 + warp;
    const __half* x = X + row * 256;

    float sum = 0.f;
    #pragma unroll
    for (int i = 0; i < 8; ++i)
        sum += __half2float(x[lane + i * 32]) * ws[lane + i * 32];
    #pragma unroll
    for (int off = 16; off; off >>= 1) sum += __shfl_xor_sync(0xffffffffu, sum, off);
    if (lane == 0) out[row] = sum + b[0];
}

// =====================================================================
// Launch
// =====================================================================
extern "C" void kernel_launch(void* const* d_in, const int* in_sizes, int n_in,
                              void* d_out, int out_size)
{
    (void)in_sizes; (void)n_in; (void)out_size;
    const float* dense = (const float*)d_in[0];
    const int*   sidx  = (const int*)d_in[1];
    const float* emb   = (const float*)d_in[2];
    const float* bw0 = (const float*)d_in[3];
    const float* bb0 = (const float*)d_in[4];
    const float* bw1 = (const float*)d_in[5];
    const float* bb1 = (const float*)d_in[6];
    const float* bw2 = (const float*)d_in[7];
    const float* bb2 = (const float*)d_in[8];
    const float* tw0 = (const float*)d_in[9];
    const float* tb0 = (const float*)d_in[10];
    const float* tw1 = (const float*)d_in[11];
    const float* tb1 = (const float*)d_in[12];
    const float* tw2 = (const float*)d_in[13];
    const float* tb2 = (const float*)d_in[14];
    const float* tw3 = (const float*)d_in[15];
    const float* tb3 = (const float*)d_in[16];
    const float* tw4 = (const float*)d_in[17];
    const float* tb4 = (const float*)d_in[18];
    float* out = (float*)d_out;

    __half *A = nullptr, *B = nullptr, *H = nullptr, *WT = nullptr;
    cudaGetSymbolAddress((void**)&A, g_bufA);
    cudaGetSymbolAddress((void**)&B, g_bufB);
    cudaGetSymbolAddress((void**)&H, g_h);
    cudaGetSymbolAddress((void**)&WT, g_wt);

    static int attr_done = 0;
    if (!attr_done) {
        cudaFuncSetAttribute(gemm_fp16, cudaFuncAttributeMaxDynamicSharedMemorySize, GSMEM);
        attr_done = 1;
    }

    const dim3 tb(32, 8);
    transpose_w<<<dim3(16, 8),  tb>>>(bw1, WT + WT_BW1, 512,  256,  512);
    transpose_w<<<dim3(8, 4),   tb>>>(bw2, WT + WT_BW2, 256,  128,  256);
    transpose_w<<<dim3(16, 32), tb>>>(tw0, WT + WT_TW0, 506,  1024, 512);
    transpose_w<<<dim3(32, 32), tb>>>(tw1, WT + WT_TW1, 1024, 1024, 1024);
    transpose_w<<<dim3(32, 16), tb>>>(tw2, WT + WT_TW2, 1024, 512,  1024);
    transpose_w<<<dim3(16, 8),  tb>>>(tw3, WT + WT_TW3, 512,  256,  512);

    const int MB = BATCH / 128;  // 512

    // bottom MLP: 13 -> 512 -> 256 -> 128 (relu)
    bottom0_kernel<<<BATCH / 32, 256>>>(dense, bw0, bb0, A);
    gemm_fp16<<<dim3(2, MB), 256, GSMEM>>>(A, 512, WT + WT_BW1, bb1, B, 256, 512, 1);
    gemm_fp16<<<dim3(1, MB), 256, GSMEM>>>(B, 256, WT + WT_BW2, bb2, H, 128, 256, 1);

    // gather + interaction + top_in assembly
    interact_kernel<<<BATCH / 4, 128>>>(emb, sidx, H, A);

    // top MLP: 506(pad 512) -> 1024 -> 1024 -> 512 -> 256 (relu) -> 1
    gemm_fp16<<<dim3(8, MB), 256, GSMEM>>>(A, 512,  WT + WT_TW0, tb0, B, 1024, 512,  1);
    gemm_fp16<<<dim3(8, MB), 256, GSMEM>>>(B, 1024, WT + WT_TW1, tb1, A, 1024, 1024, 1);
    gemm_fp16<<<dim3(4, MB), 256, GSMEM>>>(A, 1024, WT + WT_TW2, tb2, B, 512,  1024, 1);
    gemm_fp16<<<dim3(2, MB), 256, GSMEM>>>(B, 512,  WT + WT_TW3, tb3, A, 256,  512,  1);
    gemv_final_kernel<<<BATCH / 8, 256>>>(A, tw4, tb4, out);
}